// round 2
// baseline (speedup 1.0000x reference)
#include <cuda_runtime.h>
#include <cstdint>

// Problem constants (shapes fixed by the dataset)
#define MAX_N 100000
#define DIM   128

// Scratch: per-node accumulators.
//   g_xacc[n][0:128]   = sum over edges (dst==n) of w_e * x[src_e]
//   g_xacc[n][128:256] = sum over edges (dst==n) of w_e * edge_attr_e
//   g_s[n]             = sum over edges (dst==n) of w_e
__device__ float g_xacc[(size_t)MAX_N * 256];
__device__ float g_s[MAX_N];

// ---------------------------------------------------------------------------
// Zero the scratch (deterministic per launch; d_out is fully overwritten by
// the GEMM so it needs no init).
// ---------------------------------------------------------------------------
__global__ void zero_kernel(int N)
{
    size_t idx    = (size_t)blockIdx.x * blockDim.x + threadIdx.x;
    size_t stride = (size_t)gridDim.x * blockDim.x;
    float4* p = (float4*)g_xacc;
    size_t n4 = (size_t)N * 64;   // N*256 floats / 4
    for (size_t i = idx; i < n4; i += stride)
        p[i] = make_float4(0.f, 0.f, 0.f, 0.f);
    for (size_t i = idx; i < (size_t)N; i += stride)
        g_s[i] = 0.f;
}

// ---------------------------------------------------------------------------
// Edge scatter pass: one warp per edge, grid-stride over edges.
//   - gather x[src] row (512B, coalesced float4 per lane)
//   - stream edge_attr row (512B, coalesced)
//   - red.global.add.v4.f32 into g_xacc[dst]
// ---------------------------------------------------------------------------
__device__ __forceinline__ void red_add_v4(float* addr, float a, float b, float c, float d)
{
    asm volatile("red.global.add.v4.f32 [%0], {%1, %2, %3, %4};"
                 :: "l"(addr), "f"(a), "f"(b), "f"(c), "f"(d)
                 : "memory");
}

__global__ __launch_bounds__(256)
void edge_kernel(const float* __restrict__ x,
                 const int*   __restrict__ src,
                 const int*   __restrict__ dst,
                 const float* __restrict__ ew,
                 const float* __restrict__ ea,
                 int E)
{
    const int lane    = threadIdx.x & 31;
    const int warp0   = (int)((blockIdx.x * blockDim.x + threadIdx.x) >> 5);
    const int nwarps  = (int)((gridDim.x * blockDim.x) >> 5);

    for (int e = warp0; e < E; e += nwarps) {
        int   s = __ldg(src + e);
        int   d = __ldg(dst + e);
        float w = __ldg(ew  + e);

        float4 xv = ((const float4*)(x  + (size_t)s * DIM))[lane];
        float4 ev = ((const float4*)(ea + (size_t)e * DIM))[lane];

        float* base = g_xacc + (size_t)d * 256 + lane * 4;
        red_add_v4(base,       w * xv.x, w * xv.y, w * xv.z, w * xv.w);
        red_add_v4(base + 128, w * ev.x, w * ev.y, w * ev.z, w * ev.w);
        if (lane == 0)
            atomicAdd(&g_s[d], w);
    }
}

// ---------------------------------------------------------------------------
// Fused GEMM:  out[N,128] = A_virtual[N,512] @ Bcat[512,128]
//   A k-regions:   [0,128)  : x * s[row]      (stride 128)
//                  [128,384): g_xacc          (stride 256)
//                  [384,512): x               (stride 128)
//   B k-regions:   [0,384)  : W_msg rows      (already [W_i; W_j; W_e])
//                  [384,512): W_self rows
// Tiling: BM=128, BN=128, BK=32, 256 threads, 8x8 per thread.
// ---------------------------------------------------------------------------
#define BM 128
#define BN 128
#define BK 32
#define TM 8
#define TN 8

__global__ __launch_bounds__(256)
void gemm_kernel(const float* __restrict__ x,
                 const float* __restrict__ Wmsg,
                 const float* __restrict__ Wself,
                 float* __restrict__ out,
                 int N)
{
    __shared__ float As[BK][BM];   // transposed: As[k][m]
    __shared__ float Bs[BK][BN];

    const int tid  = threadIdx.x;
    const int row0 = blockIdx.x * BM;
    const int ty   = tid >> 4;          // 0..15 -> row group
    const int tx   = tid & 15;          // 0..15 -> col group

    float acc[TM][TN];
    #pragma unroll
    for (int i = 0; i < TM; i++)
        #pragma unroll
        for (int j = 0; j < TN; j++)
            acc[i][j] = 0.f;

    #pragma unroll 1
    for (int kc = 0; kc < 512 / BK; kc++) {
        const int k0 = kc * BK;

        const float* srcA;
        int strideA;
        bool scale = false;
        if (k0 < 128)       { srcA = x       + k0;         strideA = 128; scale = true; }
        else if (k0 < 384)  { srcA = g_xacc  + (k0 - 128); strideA = 256; }
        else                { srcA = x       + (k0 - 384); strideA = 128; }
        const float* srcB = (k0 < 384) ? (Wmsg + (size_t)k0 * 128)
                                       : (Wself + (size_t)(k0 - 384) * 128);

        __syncthreads();   // previous iteration's compute done before overwrite

        // Load A tile (128 rows x 32 k), store transposed into As[k][m]
        {
            const int kq    = (tid & 7) * 4;
            const int mbase = tid >> 3;
            #pragma unroll
            for (int i = 0; i < 4; i++) {
                int m   = mbase + i * 32;
                int row = row0 + m;
                float4 v = make_float4(0.f, 0.f, 0.f, 0.f);
                if (row < N) {
                    v = *(const float4*)(srcA + (size_t)row * strideA + kq);
                    if (scale) {
                        float sc = __ldg(&g_s[row]);
                        v.x *= sc; v.y *= sc; v.z *= sc; v.w *= sc;
                    }
                }
                As[kq + 0][m] = v.x;
                As[kq + 1][m] = v.y;
                As[kq + 2][m] = v.z;
                As[kq + 3][m] = v.w;
            }
        }
        // Load B tile (32 k x 128 n)
        {
            const int n  = (tid & 31) * 4;
            const int kb = tid >> 5;
            #pragma unroll
            for (int i = 0; i < 4; i++) {
                int k = kb + i * 8;
                *(float4*)&Bs[k][n] = *(const float4*)(srcB + (size_t)k * 128 + n);
            }
        }

        __syncthreads();

        #pragma unroll
        for (int kk = 0; kk < BK; kk++) {
            float a[TM], b[TN];
            *(float4*)&a[0] = *(const float4*)&As[kk][ty * TM];
            *(float4*)&a[4] = *(const float4*)&As[kk][ty * TM + 4];
            *(float4*)&b[0] = *(const float4*)&Bs[kk][tx * TN];
            *(float4*)&b[4] = *(const float4*)&Bs[kk][tx * TN + 4];
            #pragma unroll
            for (int i = 0; i < TM; i++)
                #pragma unroll
                for (int j = 0; j < TN; j++)
                    acc[i][j] += a[i] * b[j];
        }
    }

    // Epilogue
    #pragma unroll
    for (int i = 0; i < TM; i++) {
        int row = row0 + ty * TM + i;
        if (row < N) {
            float* o = out + (size_t)row * 128 + tx * TN;
            *(float4*)(o)     = make_float4(acc[i][0], acc[i][1], acc[i][2], acc[i][3]);
            *(float4*)(o + 4) = make_float4(acc[i][4], acc[i][5], acc[i][6], acc[i][7]);
        }
    }
}

// ---------------------------------------------------------------------------
// Launch: zero -> edge scatter -> fused GEMM (default stream, graph-capturable)
// ---------------------------------------------------------------------------
extern "C" void kernel_launch(void* const* d_in, const int* in_sizes, int n_in,
                              void* d_out, int out_size)
{
    const float* x     = (const float*)d_in[0];
    const int*   eidx  = (const int*)  d_in[1];
    const float* ew    = (const float*)d_in[2];
    const float* ea    = (const float*)d_in[3];
    const float* Wmsg  = (const float*)d_in[4];
    const float* Wself = (const float*)d_in[5];
    float*       out   = (float*)d_out;

    const int E = in_sizes[1] / 2;
    const int N = in_sizes[0] / DIM;
    const int* src = eidx;
    const int* dst = eidx + E;

    zero_kernel<<<2048, 256>>>(N);

    // one warp per edge (grid-stride), 8 warps per block
    int eblocks = 16384;
    edge_kernel<<<eblocks, 256>>>(x, src, dst, ew, ea, E);

    gemm_kernel<<<(N + BM - 1) / BM, 256>>>(x, Wmsg, Wself, out, N);
}

// round 3
// speedup vs baseline: 1.0830x; 1.0830x over previous
#include <cuda_runtime.h>
#include <cstdint>

// Problem constants (shapes fixed by the dataset)
#define MAX_N 100000
#define MAX_E 640000
#define DIM   128

// Per-node accumulators consumed by the GEMM:
//   g_xacc[n][0:128]   = sum over edges (dst==n) of w_e * x[src_e]
//   g_xacc[n][128:256] = sum over edges (dst==n) of w_e * edge_attr_e
//   g_s[n]             = sum over edges (dst==n) of w_e
__device__ float g_xacc[(size_t)MAX_N * 256];
__device__ float g_s[MAX_N];

// CSR scratch
__device__ int   g_count[MAX_N];
__device__ int   g_off[MAX_N];
__device__ int   g_cursor[MAX_N];
__device__ int   g_bsum[128];
__device__ int   g_csr_src[MAX_E];
__device__ float g_csr_w[MAX_E];
__device__ int   g_csr_eid[MAX_E];

// ---------------------------------------------------------------------------
// CSR build: zero counts -> histogram -> exclusive scan -> scatter triples
// ---------------------------------------------------------------------------
__global__ void zero_counts(int N)
{
    int i = blockIdx.x * blockDim.x + threadIdx.x;
    if (i < N) g_count[i] = 0;
}

__global__ void hist_kernel(const int* __restrict__ dst, int E)
{
    int i = blockIdx.x * blockDim.x + threadIdx.x;
    if (i < E) atomicAdd(&g_count[dst[i]], 1);
}

#define SCAN_B 1024
__global__ __launch_bounds__(SCAN_B)
void scan_block(int N)
{
    __shared__ int sh[SCAN_B];
    int i = blockIdx.x * SCAN_B + threadIdx.x;
    int v = (i < N) ? g_count[i] : 0;
    sh[threadIdx.x] = v;
    __syncthreads();
    for (int off = 1; off < SCAN_B; off <<= 1) {
        int t = (threadIdx.x >= off) ? sh[threadIdx.x - off] : 0;
        __syncthreads();
        sh[threadIdx.x] += t;
        __syncthreads();
    }
    int incl = sh[threadIdx.x];
    if (i < N) g_off[i] = incl - v;           // exclusive within block
    if (threadIdx.x == SCAN_B - 1) g_bsum[blockIdx.x] = incl;
}

__global__ __launch_bounds__(128)
void scan_sums(int nb)
{
    __shared__ int sh[128];
    int v = (threadIdx.x < nb) ? g_bsum[threadIdx.x] : 0;
    sh[threadIdx.x] = v;
    __syncthreads();
    for (int off = 1; off < 128; off <<= 1) {
        int t = (threadIdx.x >= off) ? sh[threadIdx.x - off] : 0;
        __syncthreads();
        sh[threadIdx.x] += t;
        __syncthreads();
    }
    if (threadIdx.x < nb) g_bsum[threadIdx.x] = sh[threadIdx.x] - v;  // exclusive
}

__global__ __launch_bounds__(SCAN_B)
void scan_add(int N)
{
    int i = blockIdx.x * SCAN_B + threadIdx.x;
    if (i < N) {
        int o = g_off[i] + g_bsum[blockIdx.x];
        g_off[i]    = o;
        g_cursor[i] = o;
    }
}

__global__ void scatter_kernel(const int* __restrict__ src,
                               const int* __restrict__ dst,
                               const float* __restrict__ ew,
                               int E)
{
    int e = blockIdx.x * blockDim.x + threadIdx.x;
    if (e < E) {
        int d   = dst[e];
        int pos = atomicAdd(&g_cursor[d], 1);
        g_csr_src[pos] = src[e];
        g_csr_w[pos]   = ew[e];
        g_csr_eid[pos] = e;
    }
}

// ---------------------------------------------------------------------------
// Gather pass: one warp per node, register accumulation, single clean store.
// Fully overwrites g_xacc / g_s, so no zero pass needed for them.
// ---------------------------------------------------------------------------
__global__ __launch_bounds__(256)
void gather_kernel(const float* __restrict__ x,
                   const float* __restrict__ ea,
                   int N)
{
    const int lane   = threadIdx.x & 31;
    const int warp0  = (int)((blockIdx.x * blockDim.x + threadIdx.x) >> 5);
    const int nwarps = (int)((gridDim.x * blockDim.x) >> 5);

    for (int n = warp0; n < N; n += nwarps) {
        const int start = g_off[n];
        const int deg   = g_count[n];

        float4 ax = make_float4(0.f, 0.f, 0.f, 0.f);
        float4 aE = make_float4(0.f, 0.f, 0.f, 0.f);
        float  ws = 0.f;

        for (int j = 0; j < deg; j++) {
            int   s = __ldg(g_csr_src + start + j);
            float w = __ldg(g_csr_w   + start + j);
            int   e = __ldg(g_csr_eid + start + j);

            float4 xv = __ldg((const float4*)(x  + (size_t)s * DIM) + lane);
            float4 ev = __ldg((const float4*)(ea + (size_t)e * DIM) + lane);

            ax.x += w * xv.x; ax.y += w * xv.y; ax.z += w * xv.z; ax.w += w * xv.w;
            aE.x += w * ev.x; aE.y += w * ev.y; aE.z += w * ev.z; aE.w += w * ev.w;
            ws   += w;
        }

        float* base = g_xacc + (size_t)n * 256 + lane * 4;
        *(float4*)(base)       = ax;
        *(float4*)(base + 128) = aE;
        if (lane == 0) g_s[n] = ws;
    }
}

// ---------------------------------------------------------------------------
// Fused GEMM:  out[N,128] = A_virtual[N,512] @ Bcat[512,128]
//   A k-regions:   [0,128)  : x * s[row]      (stride 128)
//                  [128,384): g_xacc          (stride 256)
//                  [384,512): x               (stride 128)
//   B k-regions:   [0,384)  : W_msg rows      (already [W_i; W_j; W_e])
//                  [384,512): W_self rows
// ---------------------------------------------------------------------------
#define BM 128
#define BN 128
#define BK 32
#define TM 8
#define TN 8

__global__ __launch_bounds__(256)
void gemm_kernel(const float* __restrict__ x,
                 const float* __restrict__ Wmsg,
                 const float* __restrict__ Wself,
                 float* __restrict__ out,
                 int N)
{
    __shared__ float As[BK][BM];   // transposed: As[k][m]
    __shared__ float Bs[BK][BN];

    const int tid  = threadIdx.x;
    const int row0 = blockIdx.x * BM;
    const int ty   = tid >> 4;          // 0..15 -> row group
    const int tx   = tid & 15;          // 0..15 -> col group

    float acc[TM][TN];
    #pragma unroll
    for (int i = 0; i < TM; i++)
        #pragma unroll
        for (int j = 0; j < TN; j++)
            acc[i][j] = 0.f;

    #pragma unroll 1
    for (int kc = 0; kc < 512 / BK; kc++) {
        const int k0 = kc * BK;

        const float* srcA;
        int strideA;
        bool scale = false;
        if (k0 < 128)       { srcA = x       + k0;         strideA = 128; scale = true; }
        else if (k0 < 384)  { srcA = g_xacc  + (k0 - 128); strideA = 256; }
        else                { srcA = x       + (k0 - 384); strideA = 128; }
        const float* srcB = (k0 < 384) ? (Wmsg + (size_t)k0 * 128)
                                       : (Wself + (size_t)(k0 - 384) * 128);

        __syncthreads();   // previous iteration's compute done before overwrite

        // Load A tile (128 rows x 32 k), store transposed into As[k][m]
        {
            const int kq    = (tid & 7) * 4;
            const int mbase = tid >> 3;
            #pragma unroll
            for (int i = 0; i < 4; i++) {
                int m   = mbase + i * 32;
                int row = row0 + m;
                float4 v = make_float4(0.f, 0.f, 0.f, 0.f);
                if (row < N) {
                    v = *(const float4*)(srcA + (size_t)row * strideA + kq);
                    if (scale) {
                        float sc = __ldg(&g_s[row]);
                        v.x *= sc; v.y *= sc; v.z *= sc; v.w *= sc;
                    }
                }
                As[kq + 0][m] = v.x;
                As[kq + 1][m] = v.y;
                As[kq + 2][m] = v.z;
                As[kq + 3][m] = v.w;
            }
        }
        // Load B tile (32 k x 128 n)
        {
            const int n  = (tid & 31) * 4;
            const int kb = tid >> 5;
            #pragma unroll
            for (int i = 0; i < 4; i++) {
                int k = kb + i * 8;
                *(float4*)&Bs[k][n] = *(const float4*)(srcB + (size_t)k * 128 + n);
            }
        }

        __syncthreads();

        #pragma unroll
        for (int kk = 0; kk < BK; kk++) {
            float a[TM], b[TN];
            *(float4*)&a[0] = *(const float4*)&As[kk][ty * TM];
            *(float4*)&a[4] = *(const float4*)&As[kk][ty * TM + 4];
            *(float4*)&b[0] = *(const float4*)&Bs[kk][tx * TN];
            *(float4*)&b[4] = *(const float4*)&Bs[kk][tx * TN + 4];
            #pragma unroll
            for (int i = 0; i < TM; i++)
                #pragma unroll
                for (int j = 0; j < TN; j++)
                    acc[i][j] += a[i] * b[j];
        }
    }

    // Epilogue
    #pragma unroll
    for (int i = 0; i < TM; i++) {
        int row = row0 + ty * TM + i;
        if (row < N) {
            float* o = out + (size_t)row * 128 + tx * TN;
            *(float4*)(o)     = make_float4(acc[i][0], acc[i][1], acc[i][2], acc[i][3]);
            *(float4*)(o + 4) = make_float4(acc[i][4], acc[i][5], acc[i][6], acc[i][7]);
        }
    }
}

// ---------------------------------------------------------------------------
// Launch: CSR build -> gather -> fused GEMM (default stream, capturable)
// ---------------------------------------------------------------------------
extern "C" void kernel_launch(void* const* d_in, const int* in_sizes, int n_in,
                              void* d_out, int out_size)
{
    const float* x     = (const float*)d_in[0];
    const int*   eidx  = (const int*)  d_in[1];
    const float* ew    = (const float*)d_in[2];
    const float* ea    = (const float*)d_in[3];
    const float* Wmsg  = (const float*)d_in[4];
    const float* Wself = (const float*)d_in[5];
    float*       out   = (float*)d_out;

    const int E = in_sizes[1] / 2;
    const int N = in_sizes[0] / DIM;
    const int* src = eidx;
    const int* dst = eidx + E;

    const int nScanBlocks = (N + SCAN_B - 1) / SCAN_B;

    zero_counts<<<(N + 255) / 256, 256>>>(N);
    hist_kernel<<<(E + 255) / 256, 256>>>(dst, E);
    scan_block<<<nScanBlocks, SCAN_B>>>(N);
    scan_sums<<<1, 128>>>(nScanBlocks);
    scan_add<<<nScanBlocks, SCAN_B>>>(N);
    scatter_kernel<<<(E + 255) / 256, 256>>>(src, dst, ew, E);

    gather_kernel<<<12544, 256>>>(x, ea, N);

    gemm_kernel<<<(N + BM - 1) / BM, 256>>>(x, Wmsg, Wself, out, N);
}

// round 4
// speedup vs baseline: 1.8231x; 1.6834x over previous
#include <cuda_runtime.h>
#include <cstdint>

// Problem constants (shapes fixed by the dataset)
#define MAX_N 100000
#define MAX_E 640000
#define DIM   128

// Per-node accumulators consumed by the GEMM:
//   g_xacc[n][0:128]   = sum over edges (dst==n) of w_e * x[src_e]
//   g_xacc[n][128:256] = sum over edges (dst==n) of w_e * edge_attr_e
//   g_s[n]             = sum over edges (dst==n) of w_e
__device__ float g_xacc[(size_t)MAX_N * 256];
__device__ float g_s[MAX_N];

// CSR scratch
__device__ int   g_count[MAX_N];
__device__ int   g_off[MAX_N];
__device__ int   g_cursor[MAX_N];
__device__ int   g_bsum[128];
__device__ int   g_csr_src[MAX_E];
__device__ float g_csr_w[MAX_E];
__device__ int   g_csr_eid[MAX_E];

// ---------------------------------------------------------------------------
// CSR build: zero counts -> histogram -> exclusive scan -> scatter triples
// ---------------------------------------------------------------------------
__global__ void zero_counts(int N)
{
    int i = blockIdx.x * blockDim.x + threadIdx.x;
    if (i < N) g_count[i] = 0;
}

__global__ void hist_kernel(const int* __restrict__ dst, int E)
{
    int i = blockIdx.x * blockDim.x + threadIdx.x;
    if (i < E) atomicAdd(&g_count[dst[i]], 1);
}

#define SCAN_B 1024
__global__ __launch_bounds__(SCAN_B)
void scan_block(int N)
{
    __shared__ int sh[SCAN_B];
    int i = blockIdx.x * SCAN_B + threadIdx.x;
    int v = (i < N) ? g_count[i] : 0;
    sh[threadIdx.x] = v;
    __syncthreads();
    for (int off = 1; off < SCAN_B; off <<= 1) {
        int t = (threadIdx.x >= off) ? sh[threadIdx.x - off] : 0;
        __syncthreads();
        sh[threadIdx.x] += t;
        __syncthreads();
    }
    int incl = sh[threadIdx.x];
    if (i < N) g_off[i] = incl - v;           // exclusive within block
    if (threadIdx.x == SCAN_B - 1) g_bsum[blockIdx.x] = incl;
}

__global__ __launch_bounds__(128)
void scan_sums(int nb)
{
    __shared__ int sh[128];
    int v = (threadIdx.x < nb) ? g_bsum[threadIdx.x] : 0;
    sh[threadIdx.x] = v;
    __syncthreads();
    for (int off = 1; off < 128; off <<= 1) {
        int t = (threadIdx.x >= off) ? sh[threadIdx.x - off] : 0;
        __syncthreads();
        sh[threadIdx.x] += t;
        __syncthreads();
    }
    if (threadIdx.x < nb) g_bsum[threadIdx.x] = sh[threadIdx.x] - v;  // exclusive
}

__global__ __launch_bounds__(SCAN_B)
void scan_add(int N)
{
    int i = blockIdx.x * SCAN_B + threadIdx.x;
    if (i < N) {
        int o = g_off[i] + g_bsum[blockIdx.x];
        g_off[i]    = o;
        g_cursor[i] = o;
    }
}

__global__ void scatter_kernel(const int* __restrict__ src,
                               const int* __restrict__ dst,
                               const float* __restrict__ ew,
                               int E)
{
    int e = blockIdx.x * blockDim.x + threadIdx.x;
    if (e < E) {
        int d   = dst[e];
        int pos = atomicAdd(&g_cursor[d], 1);
        g_csr_src[pos] = src[e];
        g_csr_w[pos]   = ew[e];
        g_csr_eid[pos] = e;
    }
}

// ---------------------------------------------------------------------------
// Gather pass: one warp per node, register accumulation, single clean store.
// ---------------------------------------------------------------------------
__global__ __launch_bounds__(256)
void gather_kernel(const float* __restrict__ x,
                   const float* __restrict__ ea,
                   int N)
{
    const int lane   = threadIdx.x & 31;
    const int warp0  = (int)((blockIdx.x * blockDim.x + threadIdx.x) >> 5);
    const int nwarps = (int)((gridDim.x * blockDim.x) >> 5);

    for (int n = warp0; n < N; n += nwarps) {
        const int start = g_off[n];
        const int deg   = g_count[n];

        float4 ax = make_float4(0.f, 0.f, 0.f, 0.f);
        float4 aE = make_float4(0.f, 0.f, 0.f, 0.f);
        float  ws = 0.f;

        for (int j = 0; j < deg; j++) {
            int   s = __ldg(g_csr_src + start + j);
            float w = __ldg(g_csr_w   + start + j);
            int   e = __ldg(g_csr_eid + start + j);

            float4 xv = __ldg((const float4*)(x  + (size_t)s * DIM) + lane);
            float4 ev = __ldg((const float4*)(ea + (size_t)e * DIM) + lane);

            ax.x += w * xv.x; ax.y += w * xv.y; ax.z += w * xv.z; ax.w += w * xv.w;
            aE.x += w * ev.x; aE.y += w * ev.y; aE.z += w * ev.z; aE.w += w * ev.w;
            ws   += w;
        }

        float* base = g_xacc + (size_t)n * 256 + lane * 4;
        *(float4*)(base)       = ax;
        *(float4*)(base + 128) = aE;
        if (lane == 0) g_s[n] = ws;
    }
}

// ---------------------------------------------------------------------------
// tf32 tensor-core GEMM:  out[N,128] = A_virtual[N,512] @ Bcat[512,128]
//   A k-regions:   [0,128)  : x * s[row]      (stride 128)
//                  [128,384): g_xacc          (stride 256)
//                  [384,512): x               (stride 128)
//   B k-regions:   [0,384)  : W_msg rows; [384,512): W_self rows
// BM=128, BN=128, BK=32; 256 threads = 8 warps in a 2(M) x 4(N) grid;
// each warp owns 64x32 via 4x4 m16n8k8 tf32 mma tiles.
// ---------------------------------------------------------------------------
#define GBM 128
#define GBK 32
#define A_STRIDE 36    // pad: fragment A reads (4g+t)%32 -> conflict-free
#define B_STRIDE 136   // pad: fragment B reads (8t+g)%32 -> conflict-free

__device__ __forceinline__ uint32_t f2tf32(float f)
{
    uint32_t u;
    asm("cvt.rna.tf32.f32 %0, %1;" : "=r"(u) : "f"(f));
    return u;
}

__device__ __forceinline__ void mma_tf32(float c[4], const uint32_t a[4], const uint32_t b[2])
{
    asm("mma.sync.aligned.m16n8k8.row.col.f32.tf32.tf32.f32 "
        "{%0,%1,%2,%3}, {%4,%5,%6,%7}, {%8,%9}, {%0,%1,%2,%3};"
        : "+f"(c[0]), "+f"(c[1]), "+f"(c[2]), "+f"(c[3])
        : "r"(a[0]), "r"(a[1]), "r"(a[2]), "r"(a[3]), "r"(b[0]), "r"(b[1]));
}

__global__ __launch_bounds__(256)
void gemm_tf32_kernel(const float* __restrict__ x,
                      const float* __restrict__ Wmsg,
                      const float* __restrict__ Wself,
                      float* __restrict__ out,
                      int N)
{
    __shared__ uint32_t As[GBM * A_STRIDE];   // [m][k], tf32 bits
    __shared__ uint32_t Bs[GBK * B_STRIDE];   // [k][n], tf32 bits

    const int tid   = threadIdx.x;
    const int lane  = tid & 31;
    const int warp  = tid >> 5;
    const int warpM = warp & 1;     // 0..1
    const int warpN = warp >> 1;    // 0..3
    const int g     = lane >> 2;    // groupID 0..7
    const int t     = lane & 3;     // threadID_in_group 0..3

    const int row0 = blockIdx.x * GBM;

    float acc[4][4][4];
    #pragma unroll
    for (int mt = 0; mt < 4; mt++)
        #pragma unroll
        for (int nt = 0; nt < 4; nt++)
            #pragma unroll
            for (int i = 0; i < 4; i++)
                acc[mt][nt][i] = 0.f;

    #pragma unroll 1
    for (int kc = 0; kc < 512 / GBK; kc++) {
        const int k0 = kc * GBK;

        const float* srcA;
        int strideA;
        bool scale = false;
        if (k0 < 128)      { srcA = x      + k0;         strideA = 128; scale = true; }
        else if (k0 < 384) { srcA = g_xacc + (k0 - 128); strideA = 256; }
        else               { srcA = x      + (k0 - 384); strideA = 128; }
        const float* srcB = (k0 < 384) ? (Wmsg + (size_t)k0 * 128)
                                       : (Wself + (size_t)(k0 - 384) * 128);

        __syncthreads();   // previous iteration's compute done before overwrite

        // Load A tile (128 rows x 32 k) -> As[m][k] (tf32-converted)
        {
            const int kq    = (tid & 7) * 4;
            const int mbase = tid >> 3;
            #pragma unroll
            for (int i = 0; i < 4; i++) {
                int m   = mbase + i * 32;
                int row = row0 + m;
                float4 v = make_float4(0.f, 0.f, 0.f, 0.f);
                if (row < N) {
                    v = *(const float4*)(srcA + (size_t)row * strideA + kq);
                    if (scale) {
                        float sc = __ldg(&g_s[row]);
                        v.x *= sc; v.y *= sc; v.z *= sc; v.w *= sc;
                    }
                }
                uint32_t* a = &As[m * A_STRIDE + kq];
                a[0] = f2tf32(v.x); a[1] = f2tf32(v.y);
                a[2] = f2tf32(v.z); a[3] = f2tf32(v.w);
            }
        }
        // Load B tile (32 k x 128 n) -> Bs[k][n] (tf32-converted)
        {
            const int n  = (tid & 31) * 4;
            const int kb = tid >> 5;
            #pragma unroll
            for (int i = 0; i < 4; i++) {
                int k = kb + i * 8;
                float4 v = *(const float4*)(srcB + (size_t)k * 128 + n);
                uint32_t* b = &Bs[k * B_STRIDE + n];
                b[0] = f2tf32(v.x); b[1] = f2tf32(v.y);
                b[2] = f2tf32(v.z); b[3] = f2tf32(v.w);
            }
        }

        __syncthreads();

        #pragma unroll
        for (int ks = 0; ks < 4; ks++) {
            const int kk = ks * 8;
            uint32_t a[4][4];
            #pragma unroll
            for (int mt = 0; mt < 4; mt++) {
                const int mrow = warpM * 64 + mt * 16;
                a[mt][0] = As[(mrow + g)     * A_STRIDE + kk + t];
                a[mt][1] = As[(mrow + 8 + g) * A_STRIDE + kk + t];
                a[mt][2] = As[(mrow + g)     * A_STRIDE + kk + t + 4];
                a[mt][3] = As[(mrow + 8 + g) * A_STRIDE + kk + t + 4];
            }
            uint32_t b[4][2];
            #pragma unroll
            for (int nt = 0; nt < 4; nt++) {
                const int nc = warpN * 32 + nt * 8 + g;
                b[nt][0] = Bs[(kk + t)     * B_STRIDE + nc];
                b[nt][1] = Bs[(kk + t + 4) * B_STRIDE + nc];
            }
            #pragma unroll
            for (int mt = 0; mt < 4; mt++)
                #pragma unroll
                for (int nt = 0; nt < 4; nt++)
                    mma_tf32(acc[mt][nt], a[mt], b[nt]);
        }
    }

    // Epilogue: c0 -> (g, 2t), c1 -> (g, 2t+1), c2/c3 -> rows +8
    #pragma unroll
    for (int mt = 0; mt < 4; mt++) {
        const int r0 = row0 + warpM * 64 + mt * 16 + g;
        const int r1 = r0 + 8;
        #pragma unroll
        for (int nt = 0; nt < 4; nt++) {
            const int c = warpN * 32 + nt * 8 + 2 * t;
            if (r0 < N)
                *(float2*)(out + (size_t)r0 * 128 + c) = make_float2(acc[mt][nt][0], acc[mt][nt][1]);
            if (r1 < N)
                *(float2*)(out + (size_t)r1 * 128 + c) = make_float2(acc[mt][nt][2], acc[mt][nt][3]);
        }
    }
}

// ---------------------------------------------------------------------------
// Launch: CSR build -> gather -> tf32 GEMM (default stream, capturable)
// ---------------------------------------------------------------------------
extern "C" void kernel_launch(void* const* d_in, const int* in_sizes, int n_in,
                              void* d_out, int out_size)
{
    const float* x     = (const float*)d_in[0];
    const int*   eidx  = (const int*)  d_in[1];
    const float* ew    = (const float*)d_in[2];
    const float* ea    = (const float*)d_in[3];
    const float* Wmsg  = (const float*)d_in[4];
    const float* Wself = (const float*)d_in[5];
    float*       out   = (float*)d_out;

    const int E = in_sizes[1] / 2;
    const int N = in_sizes[0] / DIM;
    const int* src = eidx;
    const int* dst = eidx + E;

    const int nScanBlocks = (N + SCAN_B - 1) / SCAN_B;

    zero_counts<<<(N + 255) / 256, 256>>>(N);
    hist_kernel<<<(E + 255) / 256, 256>>>(dst, E);
    scan_block<<<nScanBlocks, SCAN_B>>>(N);
    scan_sums<<<1, 128>>>(nScanBlocks);
    scan_add<<<nScanBlocks, SCAN_B>>>(N);
    scatter_kernel<<<(E + 255) / 256, 256>>>(src, dst, ew, E);

    gather_kernel<<<12544, 256>>>(x, ea, N);

    gemm_tf32_kernel<<<(N + GBM - 1) / GBM, 256>>>(x, Wmsg, Wself, out, N);
}

// round 5
// speedup vs baseline: 1.9524x; 1.0709x over previous
#include <cuda_runtime.h>
#include <cstdint>

// Problem constants (shapes fixed by the dataset)
#define MAX_N 100000
#define MAX_E 640000
#define DIM   128

// Per-node accumulators consumed by the GEMM:
//   g_xacc[n][0:128]   = sum over edges (dst==n) of w_e * x[src_e]
//   g_xacc[n][128:256] = sum over edges (dst==n) of w_e * edge_attr_e
//   g_s[n]             = sum over edges (dst==n) of w_e
__device__ float g_xacc[(size_t)MAX_N * 256];
__device__ float g_s[MAX_N];

// CSR scratch. Triple packed: {src, w_bits, eid, 0} -> one LDG.128 per edge.
__device__ int  g_count[MAX_N];
__device__ int  g_off[MAX_N];
__device__ int  g_cursor[MAX_N];
__device__ int  g_bsum[128];
__device__ int4 g_csr[MAX_E];

// ---------------------------------------------------------------------------
// CSR build: zero counts -> histogram -> exclusive scan -> scatter triples
// ---------------------------------------------------------------------------
__global__ void zero_counts(int N)
{
    int i = blockIdx.x * blockDim.x + threadIdx.x;
    if (i < N) g_count[i] = 0;
}

__global__ void hist_kernel(const int* __restrict__ dst, int E)
{
    int i = blockIdx.x * blockDim.x + threadIdx.x;
    if (i < E) atomicAdd(&g_count[dst[i]], 1);
}

#define SCAN_B 1024
__global__ __launch_bounds__(SCAN_B)
void scan_block(int N)
{
    __shared__ int sh[SCAN_B];
    int i = blockIdx.x * SCAN_B + threadIdx.x;
    int v = (i < N) ? g_count[i] : 0;
    sh[threadIdx.x] = v;
    __syncthreads();
    for (int off = 1; off < SCAN_B; off <<= 1) {
        int t = (threadIdx.x >= off) ? sh[threadIdx.x - off] : 0;
        __syncthreads();
        sh[threadIdx.x] += t;
        __syncthreads();
    }
    int incl = sh[threadIdx.x];
    if (i < N) g_off[i] = incl - v;           // exclusive within block
    if (threadIdx.x == SCAN_B - 1) g_bsum[blockIdx.x] = incl;
}

__global__ __launch_bounds__(128)
void scan_sums(int nb)
{
    __shared__ int sh[128];
    int v = (threadIdx.x < nb) ? g_bsum[threadIdx.x] : 0;
    sh[threadIdx.x] = v;
    __syncthreads();
    for (int off = 1; off < 128; off <<= 1) {
        int t = (threadIdx.x >= off) ? sh[threadIdx.x - off] : 0;
        __syncthreads();
        sh[threadIdx.x] += t;
        __syncthreads();
    }
    if (threadIdx.x < nb) g_bsum[threadIdx.x] = sh[threadIdx.x] - v;  // exclusive
}

__global__ __launch_bounds__(SCAN_B)
void scan_add(int N)
{
    int i = blockIdx.x * SCAN_B + threadIdx.x;
    if (i < N) {
        int o = g_off[i] + g_bsum[blockIdx.x];
        g_off[i]    = o;
        g_cursor[i] = o;
    }
}

__global__ void scatter_kernel(const int* __restrict__ src,
                               const int* __restrict__ dst,
                               const float* __restrict__ ew,
                               int E)
{
    int e = blockIdx.x * blockDim.x + threadIdx.x;
    if (e < E) {
        int d   = dst[e];
        int pos = atomicAdd(&g_cursor[d], 1);
        g_csr[pos] = make_int4(src[e], __float_as_int(ew[e]), e, 0);
    }
}

// ---------------------------------------------------------------------------
// Gather pass: one warp per node. 4-wide edge unroll: load 4 packed triples,
// issue all 8 row gathers before accumulating (MLP ~8 per warp).
// Fully overwrites g_xacc / g_s.
// ---------------------------------------------------------------------------
__global__ __launch_bounds__(256)
void gather_kernel(const float* __restrict__ x,
                   const float* __restrict__ ea,
                   int N)
{
    const int lane   = threadIdx.x & 31;
    const int warp0  = (int)((blockIdx.x * blockDim.x + threadIdx.x) >> 5);
    const int nwarps = (int)((gridDim.x * blockDim.x) >> 5);

    for (int n = warp0; n < N; n += nwarps) {
        const int start = g_off[n];
        const int deg   = g_count[n];

        float4 ax = make_float4(0.f, 0.f, 0.f, 0.f);
        float4 aE = make_float4(0.f, 0.f, 0.f, 0.f);
        float  ws = 0.f;

        int j = 0;
        for (; j + 4 <= deg; j += 4) {
            int4 t0 = __ldg(g_csr + start + j);
            int4 t1 = __ldg(g_csr + start + j + 1);
            int4 t2 = __ldg(g_csr + start + j + 2);
            int4 t3 = __ldg(g_csr + start + j + 3);

            float4 xv0 = __ldg((const float4*)(x + (size_t)t0.x * DIM) + lane);
            float4 xv1 = __ldg((const float4*)(x + (size_t)t1.x * DIM) + lane);
            float4 xv2 = __ldg((const float4*)(x + (size_t)t2.x * DIM) + lane);
            float4 xv3 = __ldg((const float4*)(x + (size_t)t3.x * DIM) + lane);
            float4 ev0 = __ldg((const float4*)(ea + (size_t)t0.z * DIM) + lane);
            float4 ev1 = __ldg((const float4*)(ea + (size_t)t1.z * DIM) + lane);
            float4 ev2 = __ldg((const float4*)(ea + (size_t)t2.z * DIM) + lane);
            float4 ev3 = __ldg((const float4*)(ea + (size_t)t3.z * DIM) + lane);

            float w0 = __int_as_float(t0.y), w1 = __int_as_float(t1.y);
            float w2 = __int_as_float(t2.y), w3 = __int_as_float(t3.y);

            ax.x += w0*xv0.x + w1*xv1.x; ax.x += w2*xv2.x + w3*xv3.x;
            ax.y += w0*xv0.y + w1*xv1.y; ax.y += w2*xv2.y + w3*xv3.y;
            ax.z += w0*xv0.z + w1*xv1.z; ax.z += w2*xv2.z + w3*xv3.z;
            ax.w += w0*xv0.w + w1*xv1.w; ax.w += w2*xv2.w + w3*xv3.w;
            aE.x += w0*ev0.x + w1*ev1.x; aE.x += w2*ev2.x + w3*ev3.x;
            aE.y += w0*ev0.y + w1*ev1.y; aE.y += w2*ev2.y + w3*ev3.y;
            aE.z += w0*ev0.z + w1*ev1.z; aE.z += w2*ev2.z + w3*ev3.z;
            aE.w += w0*ev0.w + w1*ev1.w; aE.w += w2*ev2.w + w3*ev3.w;
            ws   += (w0 + w1) + (w2 + w3);
        }
        for (; j < deg; j++) {
            int4  t  = __ldg(g_csr + start + j);
            float w  = __int_as_float(t.y);
            float4 xv = __ldg((const float4*)(x + (size_t)t.x * DIM) + lane);
            float4 ev = __ldg((const float4*)(ea + (size_t)t.z * DIM) + lane);
            ax.x += w * xv.x; ax.y += w * xv.y; ax.z += w * xv.z; ax.w += w * xv.w;
            aE.x += w * ev.x; aE.y += w * ev.y; aE.z += w * ev.z; aE.w += w * ev.w;
            ws   += w;
        }

        float* base = g_xacc + (size_t)n * 256 + lane * 4;
        *(float4*)(base)       = ax;
        *(float4*)(base + 128) = aE;
        if (lane == 0) g_s[n] = ws;
    }
}

// ---------------------------------------------------------------------------
// tf32 tensor-core GEMM:  out[N,128] = A_virtual[N,512] @ Bcat[512,128]
//   A k-regions:   [0,128)  : x * s[row]      (stride 128)
//                  [128,384): g_xacc          (stride 256)
//                  [384,512): x               (stride 128)
//   B k-regions:   [0,384)  : W_msg rows; [384,512): W_self rows
// ---------------------------------------------------------------------------
#define GBM 128
#define GBK 32
#define A_STRIDE 36
#define B_STRIDE 136

__device__ __forceinline__ uint32_t f2tf32(float f)
{
    uint32_t u;
    asm("cvt.rna.tf32.f32 %0, %1;" : "=r"(u) : "f"(f));
    return u;
}

__device__ __forceinline__ void mma_tf32(float c[4], const uint32_t a[4], const uint32_t b[2])
{
    asm("mma.sync.aligned.m16n8k8.row.col.f32.tf32.tf32.f32 "
        "{%0,%1,%2,%3}, {%4,%5,%6,%7}, {%8,%9}, {%0,%1,%2,%3};"
        : "+f"(c[0]), "+f"(c[1]), "+f"(c[2]), "+f"(c[3])
        : "r"(a[0]), "r"(a[1]), "r"(a[2]), "r"(a[3]), "r"(b[0]), "r"(b[1]));
}

__global__ __launch_bounds__(256)
void gemm_tf32_kernel(const float* __restrict__ x,
                      const float* __restrict__ Wmsg,
                      const float* __restrict__ Wself,
                      float* __restrict__ out,
                      int N)
{
    __shared__ uint32_t As[GBM * A_STRIDE];   // [m][k], tf32 bits
    __shared__ uint32_t Bs[GBK * B_STRIDE];   // [k][n], tf32 bits

    const int tid   = threadIdx.x;
    const int lane  = tid & 31;
    const int warp  = tid >> 5;
    const int warpM = warp & 1;     // 0..1
    const int warpN = warp >> 1;    // 0..3
    const int g     = lane >> 2;    // groupID 0..7
    const int t     = lane & 3;     // threadID_in_group 0..3

    const int row0 = blockIdx.x * GBM;

    float acc[4][4][4];
    #pragma unroll
    for (int mt = 0; mt < 4; mt++)
        #pragma unroll
        for (int nt = 0; nt < 4; nt++)
            #pragma unroll
            for (int i = 0; i < 4; i++)
                acc[mt][nt][i] = 0.f;

    #pragma unroll 1
    for (int kc = 0; kc < 512 / GBK; kc++) {
        const int k0 = kc * GBK;

        const float* srcA;
        int strideA;
        bool scale = false;
        if (k0 < 128)      { srcA = x      + k0;         strideA = 128; scale = true; }
        else if (k0 < 384) { srcA = g_xacc + (k0 - 128); strideA = 256; }
        else               { srcA = x      + (k0 - 384); strideA = 128; }
        const float* srcB = (k0 < 384) ? (Wmsg + (size_t)k0 * 128)
                                       : (Wself + (size_t)(k0 - 384) * 128);

        __syncthreads();   // previous iteration's compute done before overwrite

        // Load A tile (128 rows x 32 k) -> As[m][k] (tf32-converted)
        {
            const int kq    = (tid & 7) * 4;
            const int mbase = tid >> 3;
            #pragma unroll
            for (int i = 0; i < 4; i++) {
                int m   = mbase + i * 32;
                int row = row0 + m;
                float4 v = make_float4(0.f, 0.f, 0.f, 0.f);
                if (row < N) {
                    v = *(const float4*)(srcA + (size_t)row * strideA + kq);
                    if (scale) {
                        float sc = __ldg(&g_s[row]);
                        v.x *= sc; v.y *= sc; v.z *= sc; v.w *= sc;
                    }
                }
                uint32_t* a = &As[m * A_STRIDE + kq];
                a[0] = f2tf32(v.x); a[1] = f2tf32(v.y);
                a[2] = f2tf32(v.z); a[3] = f2tf32(v.w);
            }
        }
        // Load B tile (32 k x 128 n) -> Bs[k][n] (tf32-converted)
        {
            const int n  = (tid & 31) * 4;
            const int kb = tid >> 5;
            #pragma unroll
            for (int i = 0; i < 4; i++) {
                int k = kb + i * 8;
                float4 v = *(const float4*)(srcB + (size_t)k * 128 + n);
                uint32_t* b = &Bs[k * B_STRIDE + n];
                b[0] = f2tf32(v.x); b[1] = f2tf32(v.y);
                b[2] = f2tf32(v.z); b[3] = f2tf32(v.w);
            }
        }

        __syncthreads();

        #pragma unroll
        for (int ks = 0; ks < 4; ks++) {
            const int kk = ks * 8;
            uint32_t a[4][4];
            #pragma unroll
            for (int mt = 0; mt < 4; mt++) {
                const int mrow = warpM * 64 + mt * 16;
                a[mt][0] = As[(mrow + g)     * A_STRIDE + kk + t];
                a[mt][1] = As[(mrow + 8 + g) * A_STRIDE + kk + t];
                a[mt][2] = As[(mrow + g)     * A_STRIDE + kk + t + 4];
                a[mt][3] = As[(mrow + 8 + g) * A_STRIDE + kk + t + 4];
            }
            uint32_t b[4][2];
            #pragma unroll
            for (int nt = 0; nt < 4; nt++) {
                const int nc = warpN * 32 + nt * 8 + g;
                b[nt][0] = Bs[(kk + t)     * B_STRIDE + nc];
                b[nt][1] = Bs[(kk + t + 4) * B_STRIDE + nc];
            }
            #pragma unroll
            for (int mt = 0; mt < 4; mt++)
                #pragma unroll
                for (int nt = 0; nt < 4; nt++)
                    mma_tf32(acc[mt][nt], a[mt], b[nt]);
        }
    }

    // Epilogue: c0 -> (g, 2t), c1 -> (g, 2t+1), c2/c3 -> rows +8
    #pragma unroll
    for (int mt = 0; mt < 4; mt++) {
        const int r0 = row0 + warpM * 64 + mt * 16 + g;
        const int r1 = r0 + 8;
        #pragma unroll
        for (int nt = 0; nt < 4; nt++) {
            const int c = warpN * 32 + nt * 8 + 2 * t;
            if (r0 < N)
                *(float2*)(out + (size_t)r0 * 128 + c) = make_float2(acc[mt][nt][0], acc[mt][nt][1]);
            if (r1 < N)
                *(float2*)(out + (size_t)r1 * 128 + c) = make_float2(acc[mt][nt][2], acc[mt][nt][3]);
        }
    }
}

// ---------------------------------------------------------------------------
// Launch: CSR build -> gather -> tf32 GEMM (default stream, capturable)
// ---------------------------------------------------------------------------
extern "C" void kernel_launch(void* const* d_in, const int* in_sizes, int n_in,
                              void* d_out, int out_size)
{
    const float* x     = (const float*)d_in[0];
    const int*   eidx  = (const int*)  d_in[1];
    const float* ew    = (const float*)d_in[2];
    const float* ea    = (const float*)d_in[3];
    const float* Wmsg  = (const float*)d_in[4];
    const float* Wself = (const float*)d_in[5];
    float*       out   = (float*)d_out;

    const int E = in_sizes[1] / 2;
    const int N = in_sizes[0] / DIM;
    const int* src = eidx;
    const int* dst = eidx + E;

    const int nScanBlocks = (N + SCAN_B - 1) / SCAN_B;

    zero_counts<<<(N + 255) / 256, 256>>>(N);
    hist_kernel<<<(E + 255) / 256, 256>>>(dst, E);
    scan_block<<<nScanBlocks, SCAN_B>>>(N);
    scan_sums<<<1, 128>>>(nScanBlocks);
    scan_add<<<nScanBlocks, SCAN_B>>>(N);
    scatter_kernel<<<(E + 255) / 256, 256>>>(src, dst, ew, E);

    gather_kernel<<<12544, 256>>>(x, ea, N);

    gemm_tf32_kernel<<<(N + GBM - 1) / GBM, 256>>>(x, Wmsg, Wself, out, N);
}